// round 13
// baseline (speedup 1.0000x reference)
#include <cuda_runtime.h>
#include <math.h>

#define EPS 1e-7f

// B=32, S=2048, D=1024
#define B_ 32
#define S_ 2048
#define D_ 1024

#define KS 16                 // proj k-slices
#define DHH 64                // d-elements per slice
#define ET 32                 // e-tile per block

__device__ float g_proj[B_][D_];   // merged proj (atomicAdd; zeroed by norm for next replay)
__device__ float g_sums[B_];       // per-batch sum of a

// ---------------------------------------------------------------------------
// Kernel 1: smem-tiled GEMM block, no shuffles/tree.
// grid (32 e-tiles, 16 k-slices) = 512 blocks, 256 thr.
// Block: out tile [32e x 32b] over 64-d slice. Thread: e = t&31 (lane),
// 4 batches b = (t>>5)*4 + q. Ms padded [32][65] -> conflict-free scalar
// reads; Ys reads are warp-uniform broadcasts. 4 coalesced REDs per thread.
// ---------------------------------------------------------------------------
__global__ void proj_kernel(const float* __restrict__ y,
                            const float* __restrict__ M) {
    __shared__ float Ms[ET][DHH + 1];   // pad -> bank (e+d)%32, conflict-free
    __shared__ float Ys[B_][DHH];

    const int t = threadIdx.x;
    const int e0 = blockIdx.x * ET;
    const int d0 = blockIdx.y * DHH;

    if (blockIdx.x == 0 && blockIdx.y == 0 && t < B_) g_sums[t] = 0.0f;

    // fill tiles: 8 threads per row, 8 floats (2 float4) each, coalesced
    {
        const int row = t >> 3;
        const int c0 = (t & 7) * 8;
        const float4* ms = reinterpret_cast<const float4*>(M + (size_t)(e0 + row) * D_ + d0 + c0);
        float4 a = ms[0], b = ms[1];
        Ms[row][c0 + 0] = a.x; Ms[row][c0 + 1] = a.y; Ms[row][c0 + 2] = a.z; Ms[row][c0 + 3] = a.w;
        Ms[row][c0 + 4] = b.x; Ms[row][c0 + 5] = b.y; Ms[row][c0 + 6] = b.z; Ms[row][c0 + 7] = b.w;
        const float4* ysrc = reinterpret_cast<const float4*>(y + (size_t)row * D_ + d0 + c0);
        *reinterpret_cast<float4*>(&Ys[row][c0])     = ysrc[0];
        *reinterpret_cast<float4*>(&Ys[row][c0 + 4]) = ysrc[1];
    }
    __syncthreads();

    const int e  = t & 31;        // = lane
    const int bg = t >> 5;        // warp id -> batch group (warp-uniform)

    float acc0 = 0.f, acc1 = 0.f, acc2 = 0.f, acc3 = 0.f;
#pragma unroll
    for (int dd = 0; dd < DHH; dd += 4) {
        float m0 = Ms[e][dd + 0];
        float m1 = Ms[e][dd + 1];
        float m2 = Ms[e][dd + 2];
        float m3 = Ms[e][dd + 3];
        float4 y0 = *reinterpret_cast<const float4*>(&Ys[bg * 4 + 0][dd]);
        float4 y1 = *reinterpret_cast<const float4*>(&Ys[bg * 4 + 1][dd]);
        float4 y2 = *reinterpret_cast<const float4*>(&Ys[bg * 4 + 2][dd]);
        float4 y3 = *reinterpret_cast<const float4*>(&Ys[bg * 4 + 3][dd]);
        acc0 = fmaf(m0, y0.x, acc0); acc0 = fmaf(m1, y0.y, acc0);
        acc0 = fmaf(m2, y0.z, acc0); acc0 = fmaf(m3, y0.w, acc0);
        acc1 = fmaf(m0, y1.x, acc1); acc1 = fmaf(m1, y1.y, acc1);
        acc1 = fmaf(m2, y1.z, acc1); acc1 = fmaf(m3, y1.w, acc1);
        acc2 = fmaf(m0, y2.x, acc2); acc2 = fmaf(m1, y2.y, acc2);
        acc2 = fmaf(m2, y2.z, acc2); acc2 = fmaf(m3, y2.w, acc2);
        acc3 = fmaf(m0, y3.x, acc3); acc3 = fmaf(m1, y3.y, acc3);
        acc3 = fmaf(m2, y3.z, acc3); acc3 = fmaf(m3, y3.w, acc3);
    }

    // coalesced spread REDs (e = lane -> 128B contiguous per q)
    atomicAdd(&g_proj[bg * 4 + 0][e0 + e], acc0);
    atomicAdd(&g_proj[bg * 4 + 1][e0 + e], acc1);
    atomicAdd(&g_proj[bg * 4 + 2][e0 + e], acc2);
    atomicAdd(&g_proj[bg * 4 + 3][e0 + e], acc3);
}

// ---------------------------------------------------------------------------
// Kernel 2 (round-8 exact): warp handles TWO consecutive s-rows; masked rows
// skip their x stream; x via __ldcs. grid (S_/16, B_), block 256.
// ---------------------------------------------------------------------------
__global__ void eij_kernel(const float* __restrict__ x,
                           const int* __restrict__ mask,
                           float* __restrict__ out) {
    const int b = blockIdx.y;
    const int warp = threadIdx.x >> 5;
    const int lane = threadIdx.x & 31;
    const int s0 = blockIdx.x * 16 + warp * 2;

    __shared__ float4 sp[D_ / 4];
    __shared__ float warp_partial[8];

    const int mk0 = mask[b * S_ + s0];
    const int mk1 = mask[b * S_ + s0 + 1];

    sp[threadIdx.x] = reinterpret_cast<const float4*>(&g_proj[b][0])[threadIdx.x];
    __syncthreads();

    float d0 = 0.0f, d1 = 0.0f;
    if (mk0 != 0) {
        const float4* xv = reinterpret_cast<const float4*>(x + ((size_t)b * S_ + s0) * D_);
#pragma unroll
        for (int j = 0; j < D_ / 128; ++j) {
            const int idx = j * 32 + lane;
            float4 xa = __ldcs(xv + idx);
            float4 pa = sp[idx];
            d0 = fmaf(xa.x, pa.x, d0);
            d0 = fmaf(xa.y, pa.y, d0);
            d0 = fmaf(xa.z, pa.z, d0);
            d0 = fmaf(xa.w, pa.w, d0);
        }
    }
    if (mk1 != 0) {
        const float4* xv = reinterpret_cast<const float4*>(x + ((size_t)b * S_ + s0 + 1) * D_);
#pragma unroll
        for (int j = 0; j < D_ / 128; ++j) {
            const int idx = j * 32 + lane;
            float4 xa = __ldcs(xv + idx);
            float4 pa = sp[idx];
            d1 = fmaf(xa.x, pa.x, d1);
            d1 = fmaf(xa.y, pa.y, d1);
            d1 = fmaf(xa.z, pa.z, d1);
            d1 = fmaf(xa.w, pa.w, d1);
        }
    }
#pragma unroll
    for (int off = 16; off > 0; off >>= 1) {
        d0 += __shfl_xor_sync(0xFFFFFFFFu, d0, off);
        d1 += __shfl_xor_sync(0xFFFFFFFFu, d1, off);
    }

    float a0 = (mk0 != 0) ? __expf(tanhf(d0)) : 0.0f;
    float a1 = (mk1 != 0) ? __expf(tanhf(d1)) : 0.0f;

    if (lane == 0) {
        reinterpret_cast<float2*>(out)[(b * S_ + s0) >> 1] = make_float2(a0, a1);
        warp_partial[warp] = a0 + a1;
    }
    __syncthreads();

    if (threadIdx.x < 8) {
        float v = warp_partial[threadIdx.x];
#pragma unroll
        for (int off = 4; off > 0; off >>= 1)
            v += __shfl_xor_sync(0x000000FFu, v, off);
        if (threadIdx.x == 0) atomicAdd(&g_sums[b], v);
    }
}

// ---------------------------------------------------------------------------
// Kernel 3: out /= (sum + EPS) via float4; zero g_proj for next replay.
// ---------------------------------------------------------------------------
__global__ void norm_kernel(float* __restrict__ out) {
    const int i = blockIdx.x * blockDim.x + threadIdx.x;   // 0..16383
    const int b = i / (S_ / 4);
    float inv = 1.0f / (g_sums[b] + EPS);
    float4 v = reinterpret_cast<float4*>(out)[i];
    v.x *= inv; v.y *= inv; v.z *= inv; v.w *= inv;
    reinterpret_cast<float4*>(out)[i] = v;
    if (i < B_ * D_ / 4)
        reinterpret_cast<float4*>(g_proj)[i] = make_float4(0.f, 0.f, 0.f, 0.f);
}

extern "C" void kernel_launch(void* const* d_in, const int* in_sizes, int n_in,
                              void* d_out, int out_size) {
    const float* x    = (const float*)d_in[0];   // [32, 2048, 1024]
    const float* y    = (const float*)d_in[1];   // [32, 1024]
    const int*   mask = (const int*)d_in[2];     // [32, 2048]
    const float* M    = (const float*)d_in[3];   // [1024, 1024]
    float* out = (float*)d_out;                  // [32, 2048]

    dim3 g1(D_ / ET, KS);
    proj_kernel<<<g1, 256>>>(y, M);
    dim3 g2(S_ / 16, B_);
    eij_kernel<<<g2, 256>>>(x, mask, out);
    norm_kernel<<<(B_ * S_ / 4) / 256, 256>>>(out);
}